// round 14
// baseline (speedup 1.0000x reference)
#include <cuda_runtime.h>
#include <cuda_fp16.h>
#include <cstdint>

// Problem constants (fixed by setup_inputs: N=32768, D=512, F=64)
#define D_DIM  512
#define F_DIM  64
#define TILE_M 64           // rows per main CTA (4 warps x 16 rows)
#define NTH    128
#define NSLAB  16           // slabs of 32 k
#define STAGES 4
#define NMAIN  512
#define NPREP  80
#define GRID   (NMAIN + NPREP)   // 592 = 148 SMs x 4 CTAs (all resident)

// Stage = x1 slab (8 KB) + M slab (4 KB)
#define X_BYTES  8192
#define STG_SZ   12288
#define AUX_OFF  (STAGES * STG_SZ)        // 49152
#define SMEM_BYTES (AUX_OFF + 512)

// Scratch (device globals: allocation-free rule)
__device__ uint16_t g_Mh[D_DIM * F_DIM];   // fp16 M[k][f], written slab-by-slab
__device__ float    g_c[F_DIM];
__device__ int      g_cnt[NSLAB];
__device__ int      g_ready[NSLAB][1024];  // 32 mirror flags, 128B apart
__device__ int      g_cready[1024];

// ---------------------------------------------------------------------------
// helpers
// ---------------------------------------------------------------------------
__device__ __forceinline__ unsigned smem_u32(const void* p) {
    return (unsigned)__cvta_generic_to_shared(p);
}
__device__ __forceinline__ void cp_async16(unsigned saddr, const void* g) {
    asm volatile("cp.async.cg.shared.global [%0], [%1], 16;\n" :: "r"(saddr), "l"(g));
}
#define CP_COMMIT() asm volatile("cp.async.commit_group;\n")
#define CP_WAIT(n)  asm volatile("cp.async.wait_group %0;\n" :: "n"(n))

__device__ __forceinline__ uint32_t cvt_h2(float2 e) {
    uint32_t r;
    asm("cvt.rn.f16x2.f32 %0, %1, %2;" : "=r"(r) : "f"(e.y), "f"(e.x));
    return r;
}
__device__ __forceinline__ float2 lds64(uint32_t a) {
    float2 v;
    asm volatile("ld.shared.v2.f32 {%0, %1}, [%2];" : "=f"(v.x), "=f"(v.y) : "r"(a));
    return v;
}

#define LDMX4T(r0, r1, r2, r3, a) \
    asm volatile("ldmatrix.sync.aligned.m8n8.x4.trans.shared.b16 {%0,%1,%2,%3}, [%4];" \
                 : "=r"(r0), "=r"(r1), "=r"(r2), "=r"(r3) : "r"(a))

#define MMA16816(d, a0, a1, a2, a3, b0, b1) \
    asm volatile("mma.sync.aligned.m16n8k16.row.col.f32.f16.f16.f32 " \
                 "{%0,%1,%2,%3}, {%4,%5,%6,%7}, {%8,%9}, {%0,%1,%2,%3};" \
                 : "+f"((d)[0]), "+f"((d)[1]), "+f"((d)[2]), "+f"((d)[3]) \
                 : "r"(a0), "r"(a1), "r"(a2), "r"(a3), "r"(b0), "r"(b1))

// ---------------------------------------------------------------------------
__global__ void init_flags_kernel() {
    int i = blockIdx.x * blockDim.x + threadIdx.x;
    if (i < NSLAB) g_cnt[i] = 0;
    for (int j = i; j < NSLAB * 1024; j += 256 * 32)
        ((int*)g_ready)[j] = 0;
    if (i < 1024) g_cready[i] = 0;
}

// ---------------------------------------------------------------------------
// Fused kernel: CTAs [0,512) = main (HMMA GEMM + epilogue, R12 config),
// CTAs [512,592) = producers streaming W slab-by-slab into g_Mh.
// ---------------------------------------------------------------------------
__global__ void __launch_bounds__(NTH, 4) fused_kernel(
    const float* __restrict__ x1, const float* __restrict__ x2,
    const float* __restrict__ V,  const float* __restrict__ W,
    const float* __restrict__ b,  const float* __restrict__ U,
    float* __restrict__ out)
{
    extern __shared__ char smem[];
    uint32_t sb = smem_u32(smem);
    int tid = threadIdx.x, warp = tid >> 5, lane = tid & 31;

    if (blockIdx.x >= NMAIN) {
        // ===================== PREP role =====================
        int pid = blockIdx.x - NMAIN;            // 0..79
        float* s_x2 = (float*)smem;
        #pragma unroll
        for (int j = 0; j < 4; j++) s_x2[j * NTH + tid] = x2[j * NTH + tid];
        __syncthreads();
        const float4* x2v = reinterpret_cast<const float4*>(s_x2);
        int wg = pid * 4 + warp;                 // 0..319

        for (int s = 0; s < NSLAB; s++) {
            for (int grp = wg; grp < 512; grp += NPREP * 4) {
                int rowbase = grp * 4;           // row in slab (0..2047)
                int f = rowbase >> 5;
                int dloc = rowbase & 31;
                const float4* w0 = reinterpret_cast<const float4*>(
                    W + ((size_t)f * D_DIM + s * 32 + dloc) * D_DIM);

                float4 wv[4][4];
                #pragma unroll
                for (int r = 0; r < 4; r++)
                    #pragma unroll
                    for (int it = 0; it < 4; it++)
                        wv[r][it] = __ldcs(w0 + r * 128 + lane + it * 32);

                float a0 = 0.f, a1 = 0.f, a2 = 0.f, a3 = 0.f;
                #pragma unroll
                for (int it = 0; it < 4; it++) {
                    float4 xv = x2v[lane + it * 32];
                    a0 += wv[0][it].x * xv.x + wv[0][it].y * xv.y
                        + wv[0][it].z * xv.z + wv[0][it].w * xv.w;
                    a1 += wv[1][it].x * xv.x + wv[1][it].y * xv.y
                        + wv[1][it].z * xv.z + wv[1][it].w * xv.w;
                    a2 += wv[2][it].x * xv.x + wv[2][it].y * xv.y
                        + wv[2][it].z * xv.z + wv[2][it].w * xv.w;
                    a3 += wv[3][it].x * xv.x + wv[3][it].y * xv.y
                        + wv[3][it].z * xv.z + wv[3][it].w * xv.w;
                }
                #pragma unroll
                for (int o = 16; o; o >>= 1) {
                    a0 += __shfl_xor_sync(0xffffffffu, a0, o);
                    a1 += __shfl_xor_sync(0xffffffffu, a1, o);
                    a2 += __shfl_xor_sync(0xffffffffu, a2, o);
                    a3 += __shfl_xor_sync(0xffffffffu, a3, o);
                }
                if (lane < 4) {
                    float v = (lane == 0) ? a0 : (lane == 1) ? a1
                            : (lane == 2) ? a2 : a3;
                    int d = s * 32 + dloc + lane;
                    v += V[(size_t)f * (2 * D_DIM) + d];
                    __half hv = __float2half_rn(v);
                    g_Mh[d * F_DIM + f] = *reinterpret_cast<uint16_t*>(&hv);
                }
            }
            __threadfence();
            __syncthreads();
            if (tid == 0) {
                if (atomicAdd(&g_cnt[s], 1) == NPREP - 1) {
                    __threadfence();
                    #pragma unroll
                    for (int m = 0; m < 32; m++)
                        *(volatile int*)&g_ready[s][m * 32] = 1;
                }
            }
        }

        if (pid == 0) {
            // c[f] = V2[f]·x2 + b[f]; 4 warps x 16 f
            for (int j = 0; j < 16; j++) {
                int f = warp * 16 + j;
                const float4* vrow = reinterpret_cast<const float4*>(
                    V + (size_t)f * (2 * D_DIM) + D_DIM);
                float acc = 0.f;
                #pragma unroll
                for (int it = 0; it < 4; it++) {
                    float4 vv = vrow[lane + it * 32];
                    float4 xv = x2v[lane + it * 32];
                    acc += vv.x * xv.x + vv.y * xv.y + vv.z * xv.z + vv.w * xv.w;
                }
                #pragma unroll
                for (int o = 16; o; o >>= 1) acc += __shfl_xor_sync(0xffffffffu, acc, o);
                if (lane == 0) g_c[f] = acc + b[f];
            }
            __threadfence();
            __syncthreads();
            if (tid == 0) {
                __threadfence();
                #pragma unroll
                for (int m = 0; m < 32; m++)
                    *(volatile int*)&g_cready[m * 32] = 1;
            }
        }
        return;
    }

    // ===================== MAIN role (R12 config) =====================
    float* sc = (float*)(smem + AUX_OFF);
    float* sU = (float*)(smem + AUX_OFF + 256);
    int base = blockIdx.x * TILE_M;
    int mir = (blockIdx.x & 31) * 32;

    auto wait_flag = [&](volatile int* p) {
        if (tid == 0) {
            int ns = 128;
            while (*p == 0) { __nanosleep(ns); if (ns < 2048) ns <<= 1; }
            __threadfence();
        }
        __syncthreads();
    };

    // stage issuer: x1 slab (512 x 16B, 4/thread) + M slab (256 x 16B, 2/thread)
    auto issue_stage = [&](int s) {
        int buf = s & (STAGES - 1);
        uint32_t sbase = sb + buf * STG_SZ;
        const float* src = x1 + (size_t)base * D_DIM + s * 32;
        #pragma unroll
        for (int j = 0; j < 4; j++) {
            int i = j * NTH + tid;
            int row = i >> 3, c = i & 7;
            cp_async16(sbase + row * 128 + ((c ^ (row & 7)) * 16),
                       src + (size_t)row * D_DIM + c * 4);
        }
        #pragma unroll
        for (int j = 0; j < 2; j++) {
            int i = j * NTH + tid;
            int kl = i >> 3, nb = i & 7;
            cp_async16(sbase + X_BYTES + kl * 128 + ((nb ^ (kl & 7)) * 16),
                       g_Mh + (s * 32 + kl) * F_DIM + nb * 8);
        }
    };

    wait_flag(&g_ready[0][mir]); issue_stage(0); CP_COMMIT();
    wait_flag(&g_ready[1][mir]); issue_stage(1); CP_COMMIT();

    int g = lane >> 2, tig = lane & 3;
    int klane = lane & 15, nsel = lane >> 4;
    uint32_t rowoff = (uint32_t)(klane * 128);
    uint32_t colp[4];
    #pragma unroll
    for (int p = 0; p < 4; p++)
        colp[p] = (uint32_t)(((2 * p + nsel) * 16) ^ ((klane & 7) * 16));

    float acc[8][4];
    #pragma unroll
    for (int nt = 0; nt < 8; nt++)
        #pragma unroll
        for (int q = 0; q < 4; q++) acc[nt][q] = 0.f;

    uint32_t aoffs[2][2];
    #pragma unroll
    for (int h = 0; h < 2; h++)
        #pragma unroll
        for (int j = 0; j < 2; j++) {
            int R = warp * 16 + g + 8 * h;
            int c = j * 2 + (tig >> 1);
            aoffs[h][j] = (uint32_t)((R << 7) | (c << 1) | (tig & 1));
        }

    for (int s = 0; s < NSLAB; s++) {
        int buf = s & (STAGES - 1);
        if (s + 2 < NSLAB) {
            wait_flag(&g_ready[s + 2][mir]);
            issue_stage(s + 2);
        }
        CP_COMMIT();
        CP_WAIT(2);
        __syncthreads();

        uint32_t abase = sb + buf * STG_SZ;
        uint32_t mbase = abase + X_BYTES;
        #pragma unroll
        for (int ksub = 0; ksub < 2; ksub++) {
            uint32_t Ah[4];
            #pragma unroll
            for (int h = 0; h < 2; h++)
                #pragma unroll
                for (int j = 0; j < 2; j++) {
                    uint32_t enc = aoffs[h][j];
                    int R = enc >> 7;
                    int c = ((enc >> 1) & 0x3F) + ksub * 4;
                    int lo8 = (enc & 1) * 8;
                    uint32_t addr = abase + (R << 7)
                                  + (uint32_t)(((c ^ (R & 7)) * 16) + lo8);
                    Ah[h + 2 * j] = cvt_h2(lds64(addr));
                }

            uint32_t bbase = mbase + (uint32_t)(ksub * 16 * 128) + rowoff;
            #pragma unroll
            for (int p = 0; p < 4; p++) {
                uint32_t h0, h1, h2, h3;
                LDMX4T(h0, h1, h2, h3, bbase + colp[p]);
                MMA16816(acc[2 * p],     Ah[0], Ah[1], Ah[2], Ah[3], h0, h1);
                MMA16816(acc[2 * p + 1], Ah[0], Ah[1], Ah[2], Ah[3], h2, h3);
            }
        }
    }

    // epilogue: wait for c, then fused L1-norm/relu/@U
    wait_flag(&g_cready[mir]);
    if (tid < F_DIM) { sc[tid] = g_c[tid]; sU[tid] = U[tid]; }
    __syncthreads();

    int rowBase = base + warp * 16;
    #pragma unroll
    for (int h = 0; h < 2; h++) {
        float s = 0.f, num = 0.f;
        #pragma unroll
        for (int nt = 0; nt < 8; nt++) {
            int f0 = nt * 8 + tig * 2;
            float v0 = acc[nt][2 * h]     + sc[f0];
            float v1 = acc[nt][2 * h + 1] + sc[f0 + 1];
            s   += fabsf(v0) + fabsf(v1);
            num += fmaxf(v0, 0.f) * sU[f0] + fmaxf(v1, 0.f) * sU[f0 + 1];
        }
        s   += __shfl_xor_sync(0xffffffffu, s, 1);
        s   += __shfl_xor_sync(0xffffffffu, s, 2);
        num += __shfl_xor_sync(0xffffffffu, num, 1);
        num += __shfl_xor_sync(0xffffffffu, num, 2);
        if (tig == 0)
            out[rowBase + g + 8 * h] = num / fmaxf(s, 1e-12f);
    }
}

// ---------------------------------------------------------------------------
// launch
// ---------------------------------------------------------------------------
extern "C" void kernel_launch(void* const* d_in, const int* in_sizes, int n_in,
                              void* d_out, int out_size)
{
    const float* x1 = (const float*)d_in[0];   // (N, 512)
    const float* x2 = (const float*)d_in[1];   // (1, 512)
    const float* V  = (const float*)d_in[2];   // (64, 1024)
    const float* W  = (const float*)d_in[3];   // (64, 512, 512)
    const float* b  = (const float*)d_in[4];   // (64,)
    const float* U  = (const float*)d_in[5];   // (64, 1)
    float* out = (float*)d_out;                // (N, 1)

    cudaFuncSetAttribute(fused_kernel, cudaFuncAttributeMaxDynamicSharedMemorySize,
                         SMEM_BYTES);

    init_flags_kernel<<<32, 256>>>();
    fused_kernel<<<GRID, NTH, SMEM_BYTES>>>(x1, x2, V, W, b, U, out);
}

// round 15
// speedup vs baseline: 1.6647x; 1.6647x over previous
#include <cuda_runtime.h>
#include <cuda_fp16.h>
#include <cstdint>

// Problem constants (fixed by setup_inputs: N=32768, D=512, F=64)
#define D_DIM  512
#define F_DIM  64
#define TILE_M 64           // rows per main CTA (4 warps x 16 rows)
#define NTH    128
#define NSLAB  16           // slabs of 32 k
#define STAGES 4

// Stage = x1 slab (8 KB) + M slab (4 KB)
#define X_BYTES  8192
#define STG_SZ   12288
#define AUX_OFF  (STAGES * STG_SZ)        // 49152
#define SMEM_BYTES (AUX_OFF + 512)

// Scratch (device globals: allocation-free rule)
__device__ uint16_t g_Mh[D_DIM * F_DIM];   // fp16 M[k][f], written slab-by-slab
__device__ float    g_c[F_DIM];
__device__ int      g_cnt[NSLAB];
__device__ int      g_ready[NSLAB][1024];  // 32 mirror flags, 128B apart
__device__ int      g_cready[1024];

// ---------------------------------------------------------------------------
// helpers
// ---------------------------------------------------------------------------
__device__ __forceinline__ unsigned smem_u32(const void* p) {
    return (unsigned)__cvta_generic_to_shared(p);
}
__device__ __forceinline__ void cp_async16(unsigned saddr, const void* g) {
    asm volatile("cp.async.cg.shared.global [%0], [%1], 16;\n" :: "r"(saddr), "l"(g));
}
#define CP_COMMIT() asm volatile("cp.async.commit_group;\n")
#define CP_WAIT(n)  asm volatile("cp.async.wait_group %0;\n" :: "n"(n))

__device__ __forceinline__ uint32_t cvt_h2(float2 e) {
    uint32_t r;
    asm("cvt.rn.f16x2.f32 %0, %1, %2;" : "=r"(r) : "f"(e.y), "f"(e.x));
    return r;
}
__device__ __forceinline__ float2 lds64(uint32_t a) {
    float2 v;
    asm volatile("ld.shared.v2.f32 {%0, %1}, [%2];" : "=f"(v.x), "=f"(v.y) : "r"(a));
    return v;
}

#define LDMX4T(r0, r1, r2, r3, a) \
    asm volatile("ldmatrix.sync.aligned.m8n8.x4.trans.shared.b16 {%0,%1,%2,%3}, [%4];" \
                 : "=r"(r0), "=r"(r1), "=r"(r2), "=r"(r3) : "r"(a))

#define MMA16816(d, a0, a1, a2, a3, b0, b1) \
    asm volatile("mma.sync.aligned.m16n8k16.row.col.f32.f16.f16.f32 " \
                 "{%0,%1,%2,%3}, {%4,%5,%6,%7}, {%8,%9}, {%0,%1,%2,%3};" \
                 : "+f"((d)[0]), "+f"((d)[1]), "+f"((d)[2]), "+f"((d)[3]) \
                 : "r"(a0), "r"(a1), "r"(a2), "r"(a3), "r"(b0), "r"(b1))

// ---------------------------------------------------------------------------
__global__ void init_flags_kernel() {
    int i = blockIdx.x * blockDim.x + threadIdx.x;
    if (i < NSLAB) g_cnt[i] = 0;
    for (int j = i; j < NSLAB * 1024; j += 256 * 32)
        ((int*)g_ready)[j] = 0;
    if (i < 1024) g_cready[i] = 0;
}

// ---------------------------------------------------------------------------
// Kernel A (slab-ordered): stream W d-major -> M slab-by-slab + per-slab flags.
// 64 CTAs per slab (bids 0..1023, slab = bid>>6); bid 1024 computes c[f].
// Within slab: CTA jj covers d_loc = jj>>1, f-half = (jj&1)*32; warp w does
// 4 consecutive f at that d (4 x 2KB contiguous W rows, MLP=16).
// ---------------------------------------------------------------------------
__global__ void __launch_bounds__(256) prep_kernel(
    const float* __restrict__ x2, const float* __restrict__ V,
    const float* __restrict__ W, const float* __restrict__ b)
{
    __shared__ float s_x2[D_DIM];
    int tid = threadIdx.x;
    for (int i = tid; i < D_DIM; i += blockDim.x) s_x2[i] = x2[i];
    __syncthreads();

    int lane = tid & 31;
    int warp = tid >> 5;
    const float4* x2v = reinterpret_cast<const float4*>(s_x2);

    if (blockIdx.x < 1024) {
        int s  = blockIdx.x >> 6;
        int jj = blockIdx.x & 63;
        int d  = s * 32 + (jj >> 1);
        int f0 = (jj & 1) * 32 + warp * 4;

        float4 wv[4][4];
        #pragma unroll
        for (int r = 0; r < 4; r++) {
            const float4* wr = reinterpret_cast<const float4*>(
                W + ((size_t)(f0 + r) * D_DIM + d) * D_DIM);
            #pragma unroll
            for (int it = 0; it < 4; it++) wv[r][it] = __ldcs(&wr[lane + it * 32]);
        }

        float a[4] = {0.f, 0.f, 0.f, 0.f};
        #pragma unroll
        for (int it = 0; it < 4; it++) {
            float4 xv = x2v[lane + it * 32];
            #pragma unroll
            for (int r = 0; r < 4; r++) {
                a[r] += wv[r][it].x * xv.x + wv[r][it].y * xv.y
                      + wv[r][it].z * xv.z + wv[r][it].w * xv.w;
            }
        }
        #pragma unroll
        for (int o = 16; o; o >>= 1) {
            #pragma unroll
            for (int r = 0; r < 4; r++)
                a[r] += __shfl_xor_sync(0xffffffffu, a[r], o);
        }
        if (lane == 0) {
            #pragma unroll
            for (int r = 0; r < 4; r++) {
                int f = f0 + r;
                float v = a[r] + V[(size_t)f * (2 * D_DIM) + d];
                __half hv = __float2half_rn(v);
                g_Mh[d * F_DIM + f] = *reinterpret_cast<uint16_t*>(&hv);
            }
        }
        __threadfence();
        __syncthreads();
        if (tid == 0) {
            if (atomicAdd(&g_cnt[s], 1) == 63) {
                __threadfence();
                #pragma unroll
                for (int m = 0; m < 32; m++)
                    *(volatile int*)&g_ready[s][m * 32] = 1;
            }
        }
    } else {
        #pragma unroll
        for (int j = 0; j < 8; j++) {
            int f = warp + j * 8;
            const float4* vrow =
                reinterpret_cast<const float4*>(V + (size_t)f * (2 * D_DIM) + D_DIM);
            float acc = 0.f;
            #pragma unroll
            for (int it = 0; it < 4; it++) {
                float4 vv = vrow[lane + it * 32];
                float4 xv = x2v[lane + it * 32];
                acc += vv.x * xv.x + vv.y * xv.y + vv.z * xv.z + vv.w * xv.w;
            }
            #pragma unroll
            for (int o = 16; o; o >>= 1) acc += __shfl_xor_sync(0xffffffffu, acc, o);
            if (lane == 0) g_c[f] = acc + b[f];
        }
        __threadfence();
        __syncthreads();
        if (tid == 0) {
            __threadfence();
            #pragma unroll
            for (int m = 0; m < 32; m++)
                *(volatile int*)&g_cready[m * 32] = 1;
        }
    }
}

// ---------------------------------------------------------------------------
// Kernel B: R12 main (fp16 HMMA + fused epilogue, 4-stage cp.async) gated by
// per-slab flags. Runs CONCURRENTLY with prep via parallel graph branches.
// ---------------------------------------------------------------------------
__global__ void __launch_bounds__(NTH) main_kernel(
    const float* __restrict__ x1, const float* __restrict__ U,
    float* __restrict__ out)
{
    extern __shared__ char smem[];
    uint32_t sb = smem_u32(smem);
    float* sc = (float*)(smem + AUX_OFF);
    float* sU = (float*)(smem + AUX_OFF + 256);

    int tid = threadIdx.x, warp = tid >> 5, lane = tid & 31;
    int base = blockIdx.x * TILE_M;
    int mir = (blockIdx.x & 31) * 32;

    auto wait_flag = [&](volatile int* p) {
        if (tid == 0) {
            int ns = 128;
            while (*p == 0) { __nanosleep(ns); if (ns < 2048) ns <<= 1; }
            __threadfence();
        }
        __syncthreads();
    };

    // stage issuer: x1 slab (512 x 16B, 4/thread) + M slab (256 x 16B, 2/thread)
    auto issue_stage = [&](int s) {
        int buf = s & (STAGES - 1);
        uint32_t sbase = sb + buf * STG_SZ;
        const float* src = x1 + (size_t)base * D_DIM + s * 32;
        #pragma unroll
        for (int j = 0; j < 4; j++) {
            int i = j * NTH + tid;
            int row = i >> 3, c = i & 7;
            cp_async16(sbase + row * 128 + ((c ^ (row & 7)) * 16),
                       src + (size_t)row * D_DIM + c * 4);
        }
        #pragma unroll
        for (int j = 0; j < 2; j++) {
            int i = j * NTH + tid;
            int kl = i >> 3, nb = i & 7;
            cp_async16(sbase + X_BYTES + kl * 128 + ((nb ^ (kl & 7)) * 16),
                       g_Mh + (s * 32 + kl) * F_DIM + nb * 8);
        }
    };

    wait_flag(&g_ready[0][mir]); issue_stage(0); CP_COMMIT();
    wait_flag(&g_ready[1][mir]); issue_stage(1); CP_COMMIT();
    if (tid < F_DIM) sU[tid] = U[tid];

    int g = lane >> 2, tig = lane & 3;
    int klane = lane & 15, nsel = lane >> 4;
    uint32_t rowoff = (uint32_t)(klane * 128);
    uint32_t colp[4];
    #pragma unroll
    for (int p = 0; p < 4; p++)
        colp[p] = (uint32_t)(((2 * p + nsel) * 16) ^ ((klane & 7) * 16));

    float acc[8][4];
    #pragma unroll
    for (int nt = 0; nt < 8; nt++)
        #pragma unroll
        for (int q = 0; q < 4; q++) acc[nt][q] = 0.f;

    uint32_t aoffs[2][2];
    #pragma unroll
    for (int h = 0; h < 2; h++)
        #pragma unroll
        for (int j = 0; j < 2; j++) {
            int R = warp * 16 + g + 8 * h;
            int c = j * 2 + (tig >> 1);
            aoffs[h][j] = (uint32_t)((R << 7) | (c << 1) | (tig & 1));
        }

    for (int s = 0; s < NSLAB; s++) {
        int buf = s & (STAGES - 1);
        if (s + 2 < NSLAB) {
            wait_flag(&g_ready[s + 2][mir]);
            issue_stage(s + 2);
        }
        CP_COMMIT();
        CP_WAIT(2);
        __syncthreads();

        uint32_t abase = sb + buf * STG_SZ;
        uint32_t mbase = abase + X_BYTES;
        #pragma unroll
        for (int ksub = 0; ksub < 2; ksub++) {
            uint32_t Ah[4];
            #pragma unroll
            for (int h = 0; h < 2; h++)
                #pragma unroll
                for (int j = 0; j < 2; j++) {
                    uint32_t enc = aoffs[h][j];
                    int R = enc >> 7;
                    int c = ((enc >> 1) & 0x3F) + ksub * 4;
                    int lo8 = (enc & 1) * 8;
                    uint32_t addr = abase + (R << 7)
                                  + (uint32_t)(((c ^ (R & 7)) * 16) + lo8);
                    Ah[h + 2 * j] = cvt_h2(lds64(addr));
                }

            uint32_t bbase = mbase + (uint32_t)(ksub * 16 * 128) + rowoff;
            #pragma unroll
            for (int p = 0; p < 4; p++) {
                uint32_t h0, h1, h2, h3;
                LDMX4T(h0, h1, h2, h3, bbase + colp[p]);
                MMA16816(acc[2 * p],     Ah[0], Ah[1], Ah[2], Ah[3], h0, h1);
                MMA16816(acc[2 * p + 1], Ah[0], Ah[1], Ah[2], Ah[3], h2, h3);
            }
        }
    }

    // epilogue: wait for c, then fused L1-norm/relu/@U
    wait_flag(&g_cready[mir]);
    if (tid < F_DIM) sc[tid] = g_c[tid];
    __syncthreads();

    int rowBase = base + warp * 16;
    #pragma unroll
    for (int h = 0; h < 2; h++) {
        float s = 0.f, num = 0.f;
        #pragma unroll
        for (int nt = 0; nt < 8; nt++) {
            int f0 = nt * 8 + tig * 2;
            float v0 = acc[nt][2 * h]     + sc[f0];
            float v1 = acc[nt][2 * h + 1] + sc[f0 + 1];
            s   += fabsf(v0) + fabsf(v1);
            num += fmaxf(v0, 0.f) * sU[f0] + fmaxf(v1, 0.f) * sU[f0 + 1];
        }
        s   += __shfl_xor_sync(0xffffffffu, s, 1);
        s   += __shfl_xor_sync(0xffffffffu, s, 2);
        num += __shfl_xor_sync(0xffffffffu, num, 1);
        num += __shfl_xor_sync(0xffffffffu, num, 2);
        if (tig == 0)
            out[rowBase + g + 8 * h] = num / fmaxf(s, 1e-12f);
    }
}

// ---------------------------------------------------------------------------
// launch: fork the (capturing) default stream so prep and main become
// PARALLEL graph branches; main self-synchronizes via device flags.
// Streams/events are host-side objects (not device memory); they are created
// per call and intentionally not destroyed (destroying a stream mid-capture
// would invalidate the capture). kernel_launch is called only a handful of
// times (correctness + capture), so the leak is bounded and harmless.
// ---------------------------------------------------------------------------
extern "C" void kernel_launch(void* const* d_in, const int* in_sizes, int n_in,
                              void* d_out, int out_size)
{
    const float* x1 = (const float*)d_in[0];   // (N, 512)
    const float* x2 = (const float*)d_in[1];   // (1, 512)
    const float* V  = (const float*)d_in[2];   // (64, 1024)
    const float* W  = (const float*)d_in[3];   // (64, 512, 512)
    const float* b  = (const float*)d_in[4];   // (64,)
    const float* U  = (const float*)d_in[5];   // (64, 1)
    float* out = (float*)d_out;                // (N, 1)

    int N = in_sizes[0] / D_DIM;               // 32768

    cudaFuncSetAttribute(main_kernel, cudaFuncAttributeMaxDynamicSharedMemorySize,
                         SMEM_BYTES);

    cudaStream_t s2;
    cudaEvent_t e0, e1;
    cudaStreamCreateWithFlags(&s2, cudaStreamNonBlocking);
    cudaEventCreateWithFlags(&e0, cudaEventDisableTiming);
    cudaEventCreateWithFlags(&e1, cudaEventDisableTiming);

    // init flags on the main (capturing) stream
    init_flags_kernel<<<32, 256>>>();

    // fork: prep on side stream (launched FIRST -> scheduler priority)
    cudaEventRecord(e0, 0);
    cudaStreamWaitEvent(s2, e0, 0);
    prep_kernel<<<1024 + 1, 256, 0, s2>>>(x2, V, W, b);
    cudaEventRecord(e1, s2);

    // main on the capturing stream (parallel with prep)
    main_kernel<<<N / TILE_M, NTH, SMEM_BYTES>>>(x1, U, out);

    // join: downstream harness ops depend on both branches
    cudaStreamWaitEvent(0, e1, 0);
}

// round 16
// speedup vs baseline: 2.4770x; 1.4880x over previous
#include <cuda_runtime.h>
#include <cuda_fp16.h>
#include <cstdint>

// Problem constants (fixed by setup_inputs: N=32768, D=512, F=64)
#define D_DIM  512
#define F_DIM  64
#define TILE_M 64           // rows per CTA (4 warps x 16 rows)
#define NTH    128
#define NSLAB  16           // 16 slabs of 32 k
#define STAGES 4

// Stage = x1 slab (8 KB) + M slab (4 KB)
#define X_BYTES  8192
#define STG_SZ   12288
#define AUX_OFF  (STAGES * STG_SZ)        // 49152
#define SMEM_BYTES (AUX_OFF + 512)

// Scratch (device globals: allocation-free rule)
__device__ uint16_t g_Mh[D_DIM * F_DIM];   // fp16 M[k][f]
__device__ float    g_c[F_DIM];            // c[f] = V2[f]·x2 + b[f]

// ---------------------------------------------------------------------------
// helpers
// ---------------------------------------------------------------------------
__device__ __forceinline__ unsigned smem_u32(const void* p) {
    return (unsigned)__cvta_generic_to_shared(p);
}
__device__ __forceinline__ void cp_async16(unsigned saddr, const void* g) {
    asm volatile("cp.async.cg.shared.global [%0], [%1], 16;\n" :: "r"(saddr), "l"(g));
}
// with L2 256B prefetch hint: pulls the NEXT slab's chunk of the same x1 row
// into L2 one stage early (temporal-granularity fix for the x1 stream)
__device__ __forceinline__ void cp_async16_pf(unsigned saddr, const void* g) {
    asm volatile("cp.async.cg.shared.global.L2::256B [%0], [%1], 16;\n" :: "r"(saddr), "l"(g));
}
#define CP_COMMIT() asm volatile("cp.async.commit_group;\n")
#define CP_WAIT(n)  asm volatile("cp.async.wait_group %0;\n" :: "n"(n))

// float2 -> packed half2 (lo16 = e.x, hi16 = e.y)
__device__ __forceinline__ uint32_t cvt_h2(float2 e) {
    uint32_t r;
    asm("cvt.rn.f16x2.f32 %0, %1, %2;" : "=r"(r) : "f"(e.y), "f"(e.x));
    return r;
}
__device__ __forceinline__ float2 lds64(uint32_t a) {
    float2 v;
    asm volatile("ld.shared.v2.f32 {%0, %1}, [%2];" : "=f"(v.x), "=f"(v.y) : "r"(a));
    return v;
}

#define LDMX4T(r0, r1, r2, r3, a) \
    asm volatile("ldmatrix.sync.aligned.m8n8.x4.trans.shared.b16 {%0,%1,%2,%3}, [%4];" \
                 : "=r"(r0), "=r"(r1), "=r"(r2), "=r"(r3) : "r"(a))

#define MMA16816(d, a0, a1, a2, a3, b0, b1) \
    asm volatile("mma.sync.aligned.m16n8k16.row.col.f32.f16.f16.f32 " \
                 "{%0,%1,%2,%3}, {%4,%5,%6,%7}, {%8,%9}, {%0,%1,%2,%3};" \
                 : "+f"((d)[0]), "+f"((d)[1]), "+f"((d)[2]), "+f"((d)[3]) \
                 : "r"(a0), "r"(a1), "r"(a2), "r"(a3), "r"(b0), "r"(b1))

// ---------------------------------------------------------------------------
// Kernel A: stream W once -> M[k][f] fp16 in global; also c[f]
// (proven ~4.9 TB/s)
// ---------------------------------------------------------------------------
__global__ void __launch_bounds__(256) prep_kernel(
    const float* __restrict__ x2, const float* __restrict__ V,
    const float* __restrict__ W, const float* __restrict__ b)
{
    __shared__ float s_x2[D_DIM];
    int tid = threadIdx.x;
    for (int i = tid; i < D_DIM; i += blockDim.x) s_x2[i] = x2[i];
    __syncthreads();

    int lane = tid & 31;
    int warp = tid >> 5;
    const float4* x2v = reinterpret_cast<const float4*>(s_x2);

    if (blockIdx.x < 1024) {
        int r0 = blockIdx.x * 32 + warp * 4;   // rows r0..r0+3 of 32768

        float4 wv[4][4];
        #pragma unroll
        for (int r = 0; r < 4; r++) {
            const float4* wr =
                reinterpret_cast<const float4*>(W + (size_t)(r0 + r) * D_DIM);
            #pragma unroll
            for (int it = 0; it < 4; it++) wv[r][it] = __ldcs(&wr[lane + it * 32]);
        }

        float a[4] = {0.f, 0.f, 0.f, 0.f};
        #pragma unroll
        for (int it = 0; it < 4; it++) {
            float4 xv = x2v[lane + it * 32];
            #pragma unroll
            for (int r = 0; r < 4; r++) {
                a[r] += wv[r][it].x * xv.x + wv[r][it].y * xv.y
                      + wv[r][it].z * xv.z + wv[r][it].w * xv.w;
            }
        }
        #pragma unroll
        for (int o = 16; o; o >>= 1) {
            #pragma unroll
            for (int r = 0; r < 4; r++)
                a[r] += __shfl_xor_sync(0xffffffffu, a[r], o);
        }
        if (lane == 0) {
            #pragma unroll
            for (int r = 0; r < 4; r++) {
                int rr = r0 + r;
                int f = rr >> 9, d = rr & 511;
                float v = a[r] + V[(size_t)f * (2 * D_DIM) + d];
                __half hv = __float2half_rn(v);
                g_Mh[d * F_DIM + f] = *reinterpret_cast<uint16_t*>(&hv);
            }
        }
    } else {
        #pragma unroll
        for (int j = 0; j < 8; j++) {
            int f = warp + j * 8;
            const float4* vrow =
                reinterpret_cast<const float4*>(V + (size_t)f * (2 * D_DIM) + D_DIM);
            float acc = 0.f;
            #pragma unroll
            for (int it = 0; it < 4; it++) {
                float4 vv = vrow[lane + it * 32];
                float4 xv = x2v[lane + it * 32];
                acc += vv.x * xv.x + vv.y * xv.y + vv.z * xv.z + vv.w * xv.w;
            }
            #pragma unroll
            for (int o = 16; o; o >>= 1) acc += __shfl_xor_sync(0xffffffffu, acc, o);
            if (lane == 0) g_c[f] = acc + b[f];
        }
    }
}

// ---------------------------------------------------------------------------
// Kernel B: fp16 HMMA GEMM + fused L1-norm/relu/@U, 4-stage cp.async.
// grid=512, 128 threads (4 warps x 16 rows), 4 CTAs/SM (49KB smem each).
// x1 stage loads carry L2::256B prefetch (next slab's chunk of the same row).
// Stage s+2 issued BEFORE waiting on stage s.
// ---------------------------------------------------------------------------
__global__ void __launch_bounds__(NTH) main_kernel(
    const float* __restrict__ x1, const float* __restrict__ U,
    float* __restrict__ out)
{
    extern __shared__ char smem[];
    uint32_t sb = smem_u32(smem);
    float* sc = (float*)(smem + AUX_OFF);
    float* sU = (float*)(smem + AUX_OFF + 256);

    int tid = threadIdx.x, warp = tid >> 5, lane = tid & 31;
    int base = blockIdx.x * TILE_M;

    // stage issuer: x1 slab (512 x 16B, 4/thread) + M slab (256 x 16B, 2/thread)
    auto issue_stage = [&](int s) {
        int buf = s & (STAGES - 1);
        uint32_t sbase = sb + buf * STG_SZ;
        const float* src = x1 + (size_t)base * D_DIM + s * 32;
        #pragma unroll
        for (int j = 0; j < 4; j++) {
            int i = j * NTH + tid;
            int row = i >> 3, c = i & 7;
            cp_async16_pf(sbase + row * 128 + ((c ^ (row & 7)) * 16),
                          src + (size_t)row * D_DIM + c * 4);
        }
        #pragma unroll
        for (int j = 0; j < 2; j++) {
            int i = j * NTH + tid;
            int kl = i >> 3, nb = i & 7;
            cp_async16(sbase + X_BYTES + kl * 128 + ((nb ^ (kl & 7)) * 16),
                       g_Mh + (s * 32 + kl) * F_DIM + nb * 8);
        }
    };

    issue_stage(0);
    CP_COMMIT();
    issue_stage(1);
    CP_COMMIT();
    if (tid < F_DIM) { sc[tid] = g_c[tid]; sU[tid] = U[tid]; }

    int g = lane >> 2, tig = lane & 3;
    int klane = lane & 15, nsel = lane >> 4;
    uint32_t rowoff = (uint32_t)(klane * 128);
    uint32_t colp[4];
    #pragma unroll
    for (int p = 0; p < 4; p++)
        colp[p] = (uint32_t)(((2 * p + nsel) * 16) ^ ((klane & 7) * 16));

    float acc[8][4];
    #pragma unroll
    for (int nt = 0; nt < 8; nt++)
        #pragma unroll
        for (int q = 0; q < 4; q++) acc[nt][q] = 0.f;

    // A-frag address parts: R = row in tile, c = 16B chunk (before ksub add)
    uint32_t aoffs[2][2];
    #pragma unroll
    for (int h = 0; h < 2; h++)
        #pragma unroll
        for (int j = 0; j < 2; j++) {
            int R = warp * 16 + g + 8 * h;
            int c = j * 2 + (tig >> 1);
            aoffs[h][j] = (uint32_t)((R << 7) | (c << 1) | (tig & 1));
        }

    for (int s = 0; s < NSLAB; s++) {
        int buf = s & (STAGES - 1);
        // issue stage s+2 FIRST (buffer (s+2)%4 freed: all warps passed the
        // iter s-1 sync => stage s-2 fully consumed), then wait on stage s
        if (s + 2 < NSLAB) issue_stage(s + 2);
        CP_COMMIT();
        CP_WAIT(2);
        __syncthreads();

        uint32_t abase = sb + buf * STG_SZ;
        uint32_t mbase = abase + X_BYTES;
        #pragma unroll
        for (int ksub = 0; ksub < 2; ksub++) {
            uint32_t Ah[4];
            #pragma unroll
            for (int h = 0; h < 2; h++)
                #pragma unroll
                for (int j = 0; j < 2; j++) {
                    uint32_t enc = aoffs[h][j];
                    int R = enc >> 7;
                    int c = ((enc >> 1) & 0x3F) + ksub * 4;
                    int lo8 = (enc & 1) * 8;
                    uint32_t addr = abase + (R << 7)
                                  + (uint32_t)(((c ^ (R & 7)) * 16) + lo8);
                    Ah[h + 2 * j] = cvt_h2(lds64(addr));
                }

            uint32_t bbase = mbase + (uint32_t)(ksub * 16 * 128) + rowoff;
            #pragma unroll
            for (int p = 0; p < 4; p++) {
                uint32_t h0, h1, h2, h3;
                LDMX4T(h0, h1, h2, h3, bbase + colp[p]);
                MMA16816(acc[2 * p],     Ah[0], Ah[1], Ah[2], Ah[3], h0, h1);
                MMA16816(acc[2 * p + 1], Ah[0], Ah[1], Ah[2], Ah[3], h2, h3);
            }
        }
    }

    // epilogue: rows g and g+8; 4 tig-lanes hold the 64 f values of each row
    int rowBase = base + warp * 16;
    #pragma unroll
    for (int h = 0; h < 2; h++) {
        float s = 0.f, num = 0.f;
        #pragma unroll
        for (int nt = 0; nt < 8; nt++) {
            int f0 = nt * 8 + tig * 2;
            float v0 = acc[nt][2 * h]     + sc[f0];
            float v1 = acc[nt][2 * h + 1] + sc[f0 + 1];
            s   += fabsf(v0) + fabsf(v1);
            num += fmaxf(v0, 0.f) * sU[f0] + fmaxf(v1, 0.f) * sU[f0 + 1];
        }
        s   += __shfl_xor_sync(0xffffffffu, s, 1);
        s   += __shfl_xor_sync(0xffffffffu, s, 2);
        num += __shfl_xor_sync(0xffffffffu, num, 1);
        num += __shfl_xor_sync(0xffffffffu, num, 2);
        if (tig == 0)
            out[rowBase + g + 8 * h] = num / fmaxf(s, 1e-12f);
    }
}

// ---------------------------------------------------------------------------
// launch
// ---------------------------------------------------------------------------
extern "C" void kernel_launch(void* const* d_in, const int* in_sizes, int n_in,
                              void* d_out, int out_size)
{
    const float* x1 = (const float*)d_in[0];   // (N, 512)
    const float* x2 = (const float*)d_in[1];   // (1, 512)
    const float* V  = (const float*)d_in[2];   // (64, 1024)
    const float* W  = (const float*)d_in[3];   // (64, 512, 512)
    const float* b  = (const float*)d_in[4];   // (64,)
    const float* U  = (const float*)d_in[5];   // (64, 1)
    float* out = (float*)d_out;                // (N, 1)

    int N = in_sizes[0] / D_DIM;               // 32768

    cudaFuncSetAttribute(main_kernel, cudaFuncAttributeMaxDynamicSharedMemorySize,
                         SMEM_BYTES);

    prep_kernel<<<1024 + 1, 256>>>(x2, V, W, b);
    main_kernel<<<N / TILE_M, NTH, SMEM_BYTES>>>(x1, U, out);
}